// round 1
// baseline (speedup 1.0000x reference)
#include <cuda_runtime.h>
#include <cstddef>

#define BB 64
#define TT 512
#define DD 1024
#define NN 64
#define SCORES_ELEMS (BB*TT*NN)
#define TAGS_OFF SCORES_ELEMS
#define LOSS_OFF (SCORES_ELEMS + BB*TT)

#define L2E 1.4426950408889634f
#define LN2 0.6931471805599453f

__device__ float g_logz[BB];
__device__ float g_gold[BB];

__device__ __forceinline__ float fast_ex2(float x){ float r; asm("ex2.approx.ftz.f32 %0, %1;" : "=f"(r) : "f"(x)); return r; }
__device__ __forceinline__ float fast_lg2(float x){ float r; asm("lg2.approx.ftz.f32 %0, %1;" : "=f"(r) : "f"(x)); return r; }

// ---------------------------------------------------------------------------
// GEMM: scores[row][c] = (X[row,:] @ W[:,c] + b[c]) * mask[row]
// 512 CTAs x 256 threads; CTA tile 64 rows x 64 cols, K-chunks of 64.
// ---------------------------------------------------------------------------
__global__ __launch_bounds__(256) void gemm_kernel(
    const float* __restrict__ X, const float* __restrict__ W,
    const float* __restrict__ bias, const int* __restrict__ mask,
    float* __restrict__ out)
{
    __shared__ __align__(16) float As[64][68];
    __shared__ __align__(16) float Ws[64][64];
    const int tid = threadIdx.x;
    const int rowbase = blockIdx.x * 64;
    const int rg = tid >> 4;         // 0..15
    const int cg = tid & 15;         // 0..15
    const int r0 = rg * 4, c0 = cg * 4;

    float acc[4][4];
    #pragma unroll
    for (int i = 0; i < 4; i++)
        #pragma unroll
        for (int c = 0; c < 4; c++) acc[i][c] = 0.f;

    for (int kk = 0; kk < DD; kk += 64) {
        #pragma unroll
        for (int p = 0; p < 4; p++) {
            int idx = tid + p * 256;
            int r = idx >> 4, q = idx & 15;
            float4 v = *(const float4*)&X[(size_t)(rowbase + r) * DD + kk + q * 4];
            *(float4*)&As[r][q * 4] = v;
        }
        #pragma unroll
        for (int p = 0; p < 4; p++) {
            int idx = tid + p * 256;
            int r = idx >> 4, q = idx & 15;
            float4 v = *(const float4*)&W[(size_t)(kk + r) * NN + q * 4];
            *(float4*)&Ws[r][q * 4] = v;
        }
        __syncthreads();
        #pragma unroll
        for (int k = 0; k < 64; k++) {
            float a0 = As[r0 + 0][k];
            float a1 = As[r0 + 1][k];
            float a2 = As[r0 + 2][k];
            float a3 = As[r0 + 3][k];
            float4 w = *(const float4*)&Ws[k][c0];
            acc[0][0] = fmaf(a0, w.x, acc[0][0]); acc[0][1] = fmaf(a0, w.y, acc[0][1]);
            acc[0][2] = fmaf(a0, w.z, acc[0][2]); acc[0][3] = fmaf(a0, w.w, acc[0][3]);
            acc[1][0] = fmaf(a1, w.x, acc[1][0]); acc[1][1] = fmaf(a1, w.y, acc[1][1]);
            acc[1][2] = fmaf(a1, w.z, acc[1][2]); acc[1][3] = fmaf(a1, w.w, acc[1][3]);
            acc[2][0] = fmaf(a2, w.x, acc[2][0]); acc[2][1] = fmaf(a2, w.y, acc[2][1]);
            acc[2][2] = fmaf(a2, w.z, acc[2][2]); acc[2][3] = fmaf(a2, w.w, acc[2][3]);
            acc[3][0] = fmaf(a3, w.x, acc[3][0]); acc[3][1] = fmaf(a3, w.y, acc[3][1]);
            acc[3][2] = fmaf(a3, w.z, acc[3][2]); acc[3][3] = fmaf(a3, w.w, acc[3][3]);
        }
        __syncthreads();
    }
    float4 bv = *(const float4*)&bias[c0];
    #pragma unroll
    for (int i = 0; i < 4; i++) {
        int row = rowbase + r0 + i;
        float mf = (float)mask[row];
        float4 o;
        o.x = (acc[i][0] + bv.x) * mf;
        o.y = (acc[i][1] + bv.y) * mf;
        o.z = (acc[i][2] + bv.z) * mf;
        o.w = (acc[i][3] + bv.w) * mf;
        *(float4*)&out[(size_t)row * NN + c0] = o;
    }
}

// ---------------------------------------------------------------------------
// CRF kernel: blocks 0..63 = log-partition + gold score; 64..127 = Viterbi.
// 128 threads: thread t handles tag j = t>>1, i-half h = t&1 (partner = lane^1).
// ---------------------------------------------------------------------------
struct VitSm {
    unsigned char bp[(TT - 1) * NN];   // 32704 B
    float alpha[NN];
    int   tag[TT];
    int   mk[TT];
};
struct LseSm {
    float alpha[NN];
    float p[NN];
    float redf[4];
    int   redi[4];
    int   lab[TT];
    int   mk[TT];
};
union CrfSm { VitSm v; LseSm l; };

__global__ __launch_bounds__(128) void crf_kernel(
    const float* __restrict__ scores, const int* __restrict__ mask,
    const int* __restrict__ labels, const float* __restrict__ trans,
    const float* __restrict__ startv, const float* __restrict__ endv,
    float* __restrict__ out_tags)
{
    __shared__ __align__(16) CrfSm sm;
    const int tid = threadIdx.x;
    const int j  = tid >> 1;
    const int h  = tid & 1;
    const int i0 = h * 32;

    if (blockIdx.x < BB) {
        // ================= LOG PARTITION + GOLD =================
        const int b = blockIdx.x;
        for (int t = tid; t < TT; t += 128) {
            sm.l.mk[t]  = mask[b * TT + t];
            sm.l.lab[t] = labels[b * TT + t];
        }
        float E[32];
        #pragma unroll
        for (int i = 0; i < 32; i++) E[i] = fast_ex2(trans[(i0 + i) * NN + j] * L2E);
        const float* srow = scores + (size_t)b * TT * NN + j;
        float alpha = 0.f;
        if (h == 0) { alpha = startv[j] + srow[0]; sm.l.alpha[j] = alpha; }
        __syncthreads();

        float emit_next = srow[NN];
        for (int t = 1; t < TT; t++) {
            float emit = emit_next;
            if (t + 1 < TT) emit_next = srow[(size_t)(t + 1) * NN];
            // m need not be the exact max (alpha spread is bounded ~12): use alpha[0]
            float m = sm.l.alpha[0];
            if (h == 0) sm.l.p[j] = fast_ex2((alpha - m) * L2E);
            __syncthreads();
            float s0 = 0.f, s1 = 0.f, s2 = 0.f, s3 = 0.f;
            #pragma unroll
            for (int i = 0; i < 32; i += 4) {
                float4 pv = *(const float4*)&sm.l.p[i0 + i];
                s0 = fmaf(pv.x, E[i + 0], s0);
                s1 = fmaf(pv.y, E[i + 1], s1);
                s2 = fmaf(pv.z, E[i + 2], s2);
                s3 = fmaf(pv.w, E[i + 3], s3);
            }
            float s = (s0 + s1) + (s2 + s3);
            s += __shfl_xor_sync(0xffffffffu, s, 1);   // combine i-halves (adjacent lanes)
            if (h == 0) {
                float na = fmaf(fast_lg2(s), LN2, m) + emit;
                if (sm.l.mk[t]) alpha = na;
                sm.l.alpha[j] = alpha;
            }
            __syncthreads();
        }
        // final logsumexp(alpha + end)
        if (h == 0) sm.l.p[j] = alpha + endv[j];
        __syncthreads();
        if (tid < 32) {
            float a0 = sm.l.p[tid], a1 = sm.l.p[tid + 32];
            float m2 = sm.l.p[0];
            float ss = fast_ex2((a0 - m2) * L2E) + fast_ex2((a1 - m2) * L2E);
            #pragma unroll
            for (int off = 16; off; off >>= 1) ss += __shfl_xor_sync(0xffffffffu, ss, off);
            if (tid == 0) g_logz[b] = fmaf(fast_lg2(ss), LN2, m2);
        }
        // gold score
        float acc = 0.f; int cnt = 0;
        for (int t = tid; t < TT; t += 128) {
            int mkv = sm.l.mk[t];
            int lt = sm.l.lab[t];
            float mf = (float)mkv;
            acc += scores[((size_t)(b * TT + t)) * NN + lt] * mf;
            if (t > 0) acc += trans[sm.l.lab[t - 1] * NN + lt] * mf;
            cnt += mkv;
        }
        #pragma unroll
        for (int off = 16; off; off >>= 1) {
            acc += __shfl_xor_sync(0xffffffffu, acc, off);
            cnt += __shfl_xor_sync(0xffffffffu, cnt, off);
        }
        int w = tid >> 5;
        if ((tid & 31) == 0) { sm.l.redf[w] = acc; sm.l.redi[w] = cnt; }
        __syncthreads();
        if (tid == 0) {
            float a = sm.l.redf[0] + sm.l.redf[1] + sm.l.redf[2] + sm.l.redf[3];
            int c = sm.l.redi[0] + sm.l.redi[1] + sm.l.redi[2] + sm.l.redi[3];
            g_gold[b] = a + startv[sm.l.lab[0]] + endv[sm.l.lab[c - 1]];
        }
    } else {
        // ================= VITERBI =================
        const int b = blockIdx.x - BB;
        for (int t = tid; t < TT; t += 128) sm.v.mk[t] = mask[b * TT + t];
        float Tr[32];
        #pragma unroll
        for (int i = 0; i < 32; i++) Tr[i] = trans[(i0 + i) * NN + j];
        const float* srow = scores + (size_t)b * TT * NN + j;
        float alpha = 0.f;
        if (h == 0) { alpha = startv[j] + srow[0]; sm.v.alpha[j] = alpha; }
        __syncthreads();

        float emit_next = srow[NN];
        for (int t = 1; t < TT; t++) {
            float emit = emit_next;
            if (t + 1 < TT) emit_next = srow[(size_t)(t + 1) * NN];
            // 4 independent max chains to avoid one serial compare chain
            float b0 = -1e30f, b1 = -1e30f, b2 = -1e30f, b3 = -1e30f;
            int id0 = i0, id1 = i0 + 1, id2 = i0 + 2, id3 = i0 + 3;
            #pragma unroll
            for (int i = 0; i < 32; i += 4) {
                float4 av = *(const float4*)&sm.v.alpha[i0 + i];
                float v0 = av.x + Tr[i + 0];
                float v1 = av.y + Tr[i + 1];
                float v2 = av.z + Tr[i + 2];
                float v3 = av.w + Tr[i + 3];
                if (v0 > b0) { b0 = v0; id0 = i0 + i + 0; }
                if (v1 > b1) { b1 = v1; id1 = i0 + i + 1; }
                if (v2 > b2) { b2 = v2; id2 = i0 + i + 2; }
                if (v3 > b3) { b3 = v3; id3 = i0 + i + 3; }
            }
            // combine chains, tie -> smallest index (matches jnp.argmax "first")
            float best = b0; int bi = id0;
            if (b1 > best || (b1 == best && id1 < bi)) { best = b1; bi = id1; }
            if (b2 > best || (b2 == best && id2 < bi)) { best = b2; bi = id2; }
            if (b3 > best || (b3 == best && id3 < bi)) { best = b3; bi = id3; }
            float vo = __shfl_xor_sync(0xffffffffu, best, 1);
            int   io = __shfl_xor_sync(0xffffffffu, bi, 1);
            if (vo > best || (vo == best && io < bi)) { best = vo; bi = io; }
            __syncthreads();
            if (h == 0) {
                int mkv = sm.v.mk[t];
                sm.v.bp[(t - 1) * NN + j] = (unsigned char)(mkv ? bi : j);
                if (mkv) alpha = best + emit;
                sm.v.alpha[j] = alpha;
            }
            __syncthreads();
        }
        // backtrace (in shared)
        if (tid == 0) {
            float bestf = -1e30f; int cur = 0;
            for (int jj = 0; jj < NN; jj++) {
                float v = sm.v.alpha[jj] + endv[jj];
                if (v > bestf) { bestf = v; cur = jj; }
            }
            sm.v.tag[TT - 1] = cur;
            for (int t = TT - 1; t >= 1; t--) {
                cur = sm.v.bp[(t - 1) * NN + cur];
                sm.v.tag[t - 1] = cur;
            }
        }
        __syncthreads();
        for (int t = tid; t < TT; t += 128)
            out_tags[b * TT + t] = (float)(sm.v.tag[t] * sm.v.mk[t]);
    }
}

// ---------------------------------------------------------------------------
// Loss = mean(log_z - gold)
// ---------------------------------------------------------------------------
__global__ void loss_kernel(float* __restrict__ out_loss) {
    int l = threadIdx.x;  // 32 threads
    float v = (g_logz[l] - g_gold[l]) + (g_logz[l + 32] - g_gold[l + 32]);
    #pragma unroll
    for (int off = 16; off; off >>= 1) v += __shfl_xor_sync(0xffffffffu, v, off);
    if (l == 0) out_loss[0] = v * (1.0f / 64.0f);
}

extern "C" void kernel_launch(void* const* d_in, const int* in_sizes, int n_in,
                              void* d_out, int out_size) {
    const float* X      = (const float*)d_in[0];
    const int*   mask   = (const int*)d_in[1];
    const int*   labels = (const int*)d_in[2];
    const float* W      = (const float*)d_in[3];
    const float* bias   = (const float*)d_in[4];
    const float* trans  = (const float*)d_in[5];
    const float* startv = (const float*)d_in[6];
    const float* endv   = (const float*)d_in[7];
    float* out = (float*)d_out;

    gemm_kernel<<<512, 256>>>(X, W, bias, mask, out);
    crf_kernel<<<128, 128>>>(out, mask, labels, trans, startv, endv, out + TAGS_OFF);
    loss_kernel<<<1, 32>>>(out + LOSS_OFF);
}